// round 17
// baseline (speedup 1.0000x reference)
#include <cuda_runtime.h>
#include <math.h>
#include <cstdint>

#define NN 100000
#define NE 600000
#define CC 128
#define NL 3
#define NS 10

// Scratch (allocation-free rule: __device__ globals), 16B-aligned.
__device__ __align__(16) float g_m  [NN * CC];
__device__ __align__(16) float g_agg[NN * CC];
__device__ __align__(16) float g_gi [NN * 3 * CC];
__device__ __align__(16) float g_gh [NN * 3 * CC];
__device__ int g_src[NE];
__device__ int g_dst[NE];
__device__ int g_esrc[NE];      // CSR: src indices grouped by dst
__device__ int g_off[NN + 1];   // CSR row offsets
__device__ int g_deg[NN];
__device__ int g_cur[NN];
__device__ int g_bsum[98];
__device__ int g_boff[98];
__device__ int g_is64;

// ============================================================================
// Edge-index normalization (int64-vs-int32 sniffing)
// ============================================================================
__global__ void detect_k(const int* __restrict__ raw) {
    int is64 = 1;
    for (int k = 0; k < 1024; k++) {
        int lo = raw[2 * k], hi = raw[2 * k + 1];
        if (hi != 0 || lo < 0 || lo >= NN) { is64 = 0; break; }
    }
    g_is64 = is64;
}
__global__ void convert_k(const int* __restrict__ raw) {
    int e = blockIdx.x * blockDim.x + threadIdx.x;
    if (e >= NE) return;
    int s, d;
    if (g_is64) { s = raw[2 * e]; d = raw[2 * (NE + e)]; }
    else        { s = raw[e];     d = raw[NE + e]; }
    g_src[e] = min(max(s, 0), NN - 1);
    g_dst[e] = min(max(d, 0), NN - 1);
}

// ============================================================================
// CSR build (once per call). Coalesced 3-phase scan.
// ============================================================================
__global__ void count_k() {
    int e = blockIdx.x * blockDim.x + threadIdx.x;
    if (e >= NE) return;
    atomicAdd(&g_deg[g_dst[e]], 1);
}

__global__ void bsum_k() {
    __shared__ int ws[32];
    int i = blockIdx.x * 1024 + threadIdx.x;
    int v = (i < NN) ? g_deg[i] : 0;
    int lane = threadIdx.x & 31, wid = threadIdx.x >> 5;
    #pragma unroll
    for (int o = 16; o > 0; o >>= 1) v += __shfl_xor_sync(0xffffffffu, v, o);
    if (lane == 0) ws[wid] = v;
    __syncthreads();
    if (wid == 0) {
        int w = ws[lane];
        #pragma unroll
        for (int o = 16; o > 0; o >>= 1) w += __shfl_xor_sync(0xffffffffu, w, o);
        if (lane == 0) g_bsum[blockIdx.x] = w;
    }
}

__global__ void bscan_k() {
    __shared__ int sh[128];
    int t = threadIdx.x;
    int v = (t < 98) ? g_bsum[t] : 0;
    sh[t] = v;
    __syncthreads();
    #pragma unroll
    for (int o = 1; o < 128; o <<= 1) {
        int a = (t >= o) ? sh[t - o] : 0;
        __syncthreads();
        sh[t] += a;
        __syncthreads();
    }
    if (t < 98) g_boff[t] = sh[t] - v;   // exclusive
}

__global__ void off_k() {
    __shared__ int sh[1024];
    int t = threadIdx.x;
    int i = blockIdx.x * 1024 + t;
    int v = (i < NN) ? g_deg[i] : 0;
    sh[t] = v;
    __syncthreads();
    #pragma unroll
    for (int o = 1; o < 1024; o <<= 1) {
        int a = (t >= o) ? sh[t - o] : 0;
        __syncthreads();
        sh[t] += a;
        __syncthreads();
    }
    if (i < NN) {
        int off = g_boff[blockIdx.x] + sh[t] - v;
        g_off[i] = off;
        g_cur[i] = off;
    }
    if (blockIdx.x == 97 && t == 0) g_off[NN] = NE;
}

__global__ void fill_k() {
    int e = blockIdx.x * blockDim.x + threadIdx.x;
    if (e >= NE) return;
    int d = g_dst[e];
    int pos = atomicAdd(&g_cur[d], 1);
    g_esrc[pos] = g_src[e];
}

// ============================================================================
// Packed-fp32 GEMM core (fma.rn.f32x2), shared by both kernels below.
// Computes a 128x128 tile: OUT[n0+*, jg0+*] with B tile from either
//   WT (W [CoutW,128] row-major) or K-major (W [128,CoutW] row-major).
// ============================================================================
#define SMEM_TOT (2 * 128 * 128 * 4)   // 128 KB

typedef unsigned long long u64;

__device__ __forceinline__ u64 packf2(float x, float y) {
    u64 r;
    asm("mov.b64 %0, {%1, %2};" : "=l"(r) : "f"(x), "f"(y));
    return r;
}
__device__ __forceinline__ void unpackf2(u64 p, float& x, float& y) {
    asm("mov.b64 {%0, %1}, %2;" : "=f"(x), "=f"(y) : "l"(p));
}
#define FMA2(c, a, b) \
    asm("fma.rn.f32x2 %0, %1, %2, %0;" : "+l"(c) : "l"(a), "l"(b))

// loads A tile [128 rows x 128 k] from IN (guarded), B per flag, computes,
// adds optional bias, stores to OUT (row stride Cout, col offset j0).
__device__ __forceinline__ void gemm_tile(
    const float* __restrict__ IN, const float* __restrict__ W,
    const float* __restrict__ bias, float* __restrict__ OUT,
    int Nrows, int Cout, int n0, int j0, bool wt, bool has_bias,
    float* As, float* Bs)
{
    const int tid = threadIdx.x;

    #pragma unroll
    for (int i = tid; i < 128 * 32; i += 256) {
        int row = i >> 5;
        int kc  = (i & 31) << 2;
        float4 v = make_float4(0.f, 0.f, 0.f, 0.f);
        int gr = n0 + row;
        if (gr < Nrows) v = *(const float4*)(IN + (size_t)gr * CC + kc);
        *(float4*)(As + row * 128 + kc) = v;
    }

    if (wt) {
        #pragma unroll
        for (int i = tid; i < 128 * 32; i += 256) {
            int j  = i & 127;
            int kc = (i >> 7) << 2;
            float4 v = *(const float4*)(W + (size_t)(j0 + j) * 128 + kc);
            Bs[(kc + 0) * 128 + j] = v.x;
            Bs[(kc + 1) * 128 + j] = v.y;
            Bs[(kc + 2) * 128 + j] = v.z;
            Bs[(kc + 3) * 128 + j] = v.w;
        }
    } else {
        #pragma unroll
        for (int i = tid; i < 128 * 32; i += 256) {
            int k  = i >> 5;
            int jc = (i & 31) << 2;
            float4 v = *(const float4*)(W + (size_t)k * Cout + j0 + jc);
            *(float4*)(Bs + k * 128 + jc) = v;
        }
    }
    __syncthreads();

    const int tx = tid & 15, ty = tid >> 4;
    const int nt = ty * 8, jt = tx * 8;

    u64 acc[8][4];
    #pragma unroll
    for (int i = 0; i < 8; i++)
        #pragma unroll
        for (int jp = 0; jp < 4; jp++) acc[i][jp] = 0ull;

    #pragma unroll 4
    for (int k = 0; k < 128; k++) {
        float4 b0 = *(const float4*)(Bs + k * 128 + jt);
        float4 b1 = *(const float4*)(Bs + k * 128 + jt + 4);
        u64 bp[4];
        bp[0] = packf2(b0.x, b0.y);
        bp[1] = packf2(b0.z, b0.w);
        bp[2] = packf2(b1.x, b1.y);
        bp[3] = packf2(b1.z, b1.w);
        u64 ad[8];
        #pragma unroll
        for (int i = 0; i < 8; i++) {
            float a = As[(nt + i) * 128 + k];
            ad[i] = packf2(a, a);
        }
        #pragma unroll
        for (int i = 0; i < 8; i++)
            #pragma unroll
            for (int jp = 0; jp < 4; jp++)
                FMA2(acc[i][jp], ad[i], bp[jp]);
    }

    float bv[8];
    if (has_bias) {
        #pragma unroll
        for (int j = 0; j < 8; j++) bv[j] = bias[j0 + jt + j];
    }
    #pragma unroll
    for (int i = 0; i < 8; i++) {
        int gr = n0 + nt + i;
        if (gr >= Nrows) continue;
        float o[8];
        #pragma unroll
        for (int jp = 0; jp < 4; jp++)
            unpackf2(acc[i][jp], o[2 * jp], o[2 * jp + 1]);
        if (has_bias) {
            #pragma unroll
            for (int j = 0; j < 8; j++) o[j] += bv[j];
        }
        float* op = OUT + (size_t)gr * Cout + j0 + jt;
        *(float4*)(op)     = make_float4(o[0], o[1], o[2], o[3]);
        *(float4*)(op + 4) = make_float4(o[4], o[5], o[6], o[7]);
    }
}

// ---- fused h-dependent GEMMs: y==0 -> m = h@w ; y=1..3 -> gh = h@wh^T + bh
__global__ __launch_bounds__(256, 1)
void mgh_k(const float* __restrict__ h, const float* __restrict__ w,
           const float* __restrict__ wh, const float* __restrict__ bh,
           float* __restrict__ m, float* __restrict__ gh)
{
    extern __shared__ float sm[];
    float* As = sm;
    float* Bs = sm + 128 * 128;
    const int n0 = blockIdx.x * 128;
    if (blockIdx.y == 0) {
        gemm_tile(h, w, nullptr, m, NN, CC, n0, 0, false, false, As, Bs);
    } else {
        int j0 = (blockIdx.y - 1) * 128;
        gemm_tile(h, wh, bh, gh, NN, 3 * CC, n0, j0, true, true, As, Bs);
    }
}

// ---- gi GEMM: gi = agg @ wi^T + bi
__global__ __launch_bounds__(256, 1)
void gi_k(const float* __restrict__ agg, const float* __restrict__ wi,
          const float* __restrict__ bi, float* __restrict__ gi)
{
    extern __shared__ float sm[];
    float* As = sm;
    float* Bs = sm + 128 * 128;
    gemm_tile(agg, wi, bi, gi, NN, 3 * CC, blockIdx.x * 128,
              blockIdx.y * 128, true, true, As, Bs);
}

// ============================================================================
// CSR gather aggregation: agg[d] = sum_{e in CSR[d]} m[esrc[e]]
// ============================================================================
__global__ void gather_k(const float* __restrict__ m, float* __restrict__ agg)
{
    int d = blockIdx.x * 8 + (threadIdx.x >> 5);
    if (d >= NN) return;
    int lane = threadIdx.x & 31;
    int beg = g_off[d], end = g_off[d + 1];
    float4 acc = make_float4(0.f, 0.f, 0.f, 0.f);
    for (int e = beg; e < end; e++) {
        int s = g_esrc[e];
        float4 v = *(const float4*)(m + (size_t)s * CC + lane * 4);
        acc.x += v.x; acc.y += v.y; acc.z += v.z; acc.w += v.w;
    }
    *(float4*)(agg + (size_t)d * CC + lane * 4) = acc;
}

// ============================================================================
// GRU gate: h = (1-z)*tanh(i_n + r*h_n) + z*h ; optional ReLU
// ============================================================================
__global__ void gate_k(const float* __restrict__ gi, const float* __restrict__ gh,
                       float* __restrict__ h, int relu)
{
    int t = blockIdx.x * blockDim.x + threadIdx.x;
    if (t >= NN * CC) return;
    int n = t >> 7;
    int j = t & 127;
    const float* gin = gi + (size_t)n * 384;
    const float* ghn = gh + (size_t)n * 384;
    float i_r = gin[j], i_z = gin[128 + j], i_n = gin[256 + j];
    float h_r = ghn[j], h_z = ghn[128 + j], h_n = ghn[256 + j];
    float hv = h[t];
    float r = 1.f / (1.f + __expf(-(i_r + h_r)));
    float z = 1.f / (1.f + __expf(-(i_z + h_z)));
    float nn = tanhf(i_n + r * h_n);
    float o = (1.f - z) * nn + z * hv;
    if (relu) o = fmaxf(o, 0.f);
    h[t] = o;
}

// ============================================================================
extern "C" void kernel_launch(void* const* d_in, const int* in_sizes, int n_in,
                              void* d_out, int out_size)
{
    const float* x       = (const float*)d_in[0];
    const int*   ei_raw  = (const int*)d_in[1];
    const float* weights = (const float*)d_in[2];
    const float* w_ih    = (const float*)d_in[3];
    const float* w_hh    = (const float*)d_in[4];
    const float* b_ih    = (const float*)d_in[5];
    const float* b_hh    = (const float*)d_in[6];
    float* h = (float*)d_out;

    void *pm, *pagg, *pgi, *pgh, *pdeg;
    cudaGetSymbolAddress(&pm,   g_m);
    cudaGetSymbolAddress(&pagg, g_agg);
    cudaGetSymbolAddress(&pgi,  g_gi);
    cudaGetSymbolAddress(&pgh,  g_gh);
    cudaGetSymbolAddress(&pdeg, g_deg);

    cudaFuncSetAttribute(mgh_k,
                         cudaFuncAttributeMaxDynamicSharedMemorySize, SMEM_TOT);
    cudaFuncSetAttribute(gi_k,
                         cudaFuncAttributeMaxDynamicSharedMemorySize, SMEM_TOT);

    // ---- edge normalization + CSR build (once per call) ----
    detect_k<<<1, 1>>>(ei_raw);
    convert_k<<<(NE + 255) / 256, 256>>>(ei_raw);
    cudaMemsetAsync(pdeg, 0, sizeof(int) * NN);
    count_k<<<(NE + 255) / 256, 256>>>();
    bsum_k<<<98, 1024>>>();
    bscan_k<<<1, 128>>>();
    off_k<<<98, 1024>>>();
    fill_k<<<(NE + 255) / 256, 256>>>();

    // h <- x
    cudaMemcpyAsync(h, x, sizeof(float) * (size_t)NN * CC,
                    cudaMemcpyDeviceToDevice);

    const int NB = (NN + 127) / 128;  // 782

    for (int l = 0; l < NL; l++) {
        const float* wi = w_ih + (size_t)l * 3 * CC * CC;
        const float* wh = w_hh + (size_t)l * 3 * CC * CC;
        const float* bi = b_ih + (size_t)l * 3 * CC;
        const float* bh = b_hh + (size_t)l * 3 * CC;
        for (int s = 0; s < NS; s++) {
            const float* w = weights + ((size_t)l * NS + s) * CC * CC;

            // fused: m = h@w (y=0) and gh = h@wh^T + bh (y=1..3), one launch
            mgh_k<<<dim3(NB, 4), 256, SMEM_TOT>>>(
                h, w, wh, bh, (float*)pm, (float*)pgh);

            // agg = segment_sum(m[src], dst)  — CSR gather
            gather_k<<<(NN + 7) / 8, 256>>>((const float*)pm, (float*)pagg);

            // gi = agg @ wi^T + bi
            gi_k<<<dim3(NB, 3), 256, SMEM_TOT>>>(
                (const float*)pagg, wi, bi, (float*)pgi);

            int relu = (s == NS - 1 && l < NL - 1) ? 1 : 0;
            gate_k<<<(NN * CC + 255) / 256, 256>>>(
                (const float*)pgi, (const float*)pgh, h, relu);
        }
    }
}